// round 5
// baseline (speedup 1.0000x reference)
#include <cuda_runtime.h>
#include <cuda_bf16.h>
#include <cstddef>

#define COL    4096
#define TPB    128
#define WPB    (TPB/32)       // 4 warps per block, one row per warp
#define NCHUNK 16             // 16 chunk-pairs x 256 elements
#define SMEM_BYTES (WPB * COL * 4)   // 64 KB: one row per warp

// Reciprocal table 1/(i+1), filled each launch (graph-capturable, no allocs).
__device__ float g_rinv[COL];

__global__ void rinv_init_kernel() {
    int i = blockIdx.x * blockDim.x + threadIdx.x;
    if (i < COL) g_rinv[i] = 1.0f / (float)(i + 1);
}

extern __shared__ float4 s_rows[];   // [WPB][1024] float4

__global__ __launch_bounds__(TPB) void layernorm_v2_kernel(
    const float* __restrict__ x,
    const float* __restrict__ alpha,
    const float* __restrict__ beta,
    float* __restrict__ out)
{
    const int lane = threadIdx.x & 31;
    const int wid  = threadIdx.x >> 5;
    const size_t row = (size_t)blockIdx.x * WPB + wid;

    const float4* xr = (const float4*)(x + row * COL);
    const float4* rr = (const float4*)g_rinv;
    float4*       orw = (float4*)(out + row * COL);
    float4*       sw  = s_rows + wid * (COL / 4);   // this warp's row buffer

    // ---- pass 1: stream row once, scan + variance, stage into smem ----
    float4 a = xr[lane];            // half-chunk A of chunk 0
    float4 b = xr[32 + lane];       // half-chunk B of chunk 0
    float carry = 0.0f;
    float acc   = 0.0f;

    #pragma unroll 1
    for (int c = 0; c < NCHUNK; ++c) {
        const int base = c * 64 + lane;

        // prefetch next chunk-pair (LDG in flight across this chunk's compute)
        float4 na, nb;
        if (c + 1 < NCHUNK) {
            na = xr[(c + 1) * 64 + lane];
            nb = xr[(c + 1) * 64 + 32 + lane];
        }

        const float4 ra = rr[base];        // L1-resident reciprocal table
        const float4 rb = rr[base + 32];

        // local inclusive scans (two independent 4-chains)
        const float pa0 = a.x;
        const float pa1 = pa0 + a.y;
        const float pa2 = pa1 + a.z;
        const float pa3 = pa2 + a.w;
        const float pb0 = b.x;
        const float pb1 = pb0 + b.y;
        const float pb2 = pb1 + b.z;
        const float pb3 = pb2 + b.w;
        const float ta = pa3, tb = pb3;

        // two interleaved warp scans (independent shfl chains, ILP 2)
        float va = ta, vb = tb;
        #pragma unroll
        for (int o = 1; o < 32; o <<= 1) {
            float sa = __shfl_up_sync(0xffffffffu, va, o);
            float sb = __shfl_up_sync(0xffffffffu, vb, o);
            if (lane >= o) { va += sa; vb += sb; }
        }
        const float totA = __shfl_sync(0xffffffffu, va, 31);
        const float totB = __shfl_sync(0xffffffffu, vb, 31);

        const float exclA = carry + (va - ta);
        const float exclB = carry + totA + (vb - tb);

        // variance against running mean
        float d0 = a.x - (exclA + pa0) * ra.x;
        float d1 = a.y - (exclA + pa1) * ra.y;
        float d2 = a.z - (exclA + pa2) * ra.z;
        float d3 = a.w - (exclA + pa3) * ra.w;
        float d4 = b.x - (exclB + pb0) * rb.x;
        float d5 = b.y - (exclB + pb1) * rb.y;
        float d6 = b.z - (exclB + pb2) * rb.z;
        float d7 = b.w - (exclB + pb3) * rb.w;
        acc += ((d0 * d0 + d1 * d1) + (d2 * d2 + d3 * d3))
             + ((d4 * d4 + d5 * d5) + (d6 * d6 + d7 * d7));

        // stage into smem (conflict-free: lane-contiguous 16B stride)
        sw[base]      = a;
        sw[base + 32] = b;

        carry += totA + totB;
        a = na;
        b = nb;
    }

    // ---- warp-local stats (no barriers anywhere) ----
    #pragma unroll
    for (int o = 16; o > 0; o >>= 1) acc += __shfl_xor_sync(0xffffffffu, acc, o);

    const float var   = acc   * (1.0f / (float)(COL - 1));
    const float mean  = carry * (1.0f / (float)COL);
    const float scale = __ldg(alpha) * rsqrtf(var + 1e-5f);
    const float be    = __ldg(beta);

    // ---- pass 2: read row from smem, write normalized output ----
    #pragma unroll 4
    for (int c = 0; c < NCHUNK; ++c) {
        const int base = c * 64 + lane;
        float4 u = sw[base];
        float4 v = sw[base + 32];
        float4 ou, ov;
        ou.x = (u.x - mean) * scale + be;
        ou.y = (u.y - mean) * scale + be;
        ou.z = (u.z - mean) * scale + be;
        ou.w = (u.w - mean) * scale + be;
        ov.x = (v.x - mean) * scale + be;
        ov.y = (v.y - mean) * scale + be;
        ov.z = (v.z - mean) * scale + be;
        ov.w = (v.w - mean) * scale + be;
        orw[base]      = ou;
        orw[base + 32] = ov;
    }
}

extern "C" void kernel_launch(void* const* d_in, const int* in_sizes, int n_in,
                              void* d_out, int out_size)
{
    const float* x     = (const float*)d_in[0];
    const float* alpha = (const float*)d_in[1];
    const float* beta  = (const float*)d_in[2];
    float*       out   = (float*)d_out;

    const int rows = in_sizes[0] / COL;
    const int grid = rows / WPB;               // 8192 blocks x 4 warp-rows

    static int smem_set = 0;
    if (!smem_set) {
        cudaFuncSetAttribute(layernorm_v2_kernel,
                             cudaFuncAttributeMaxDynamicSharedMemorySize,
                             SMEM_BYTES);
        smem_set = 1;
    }

    rinv_init_kernel<<<(COL + 255) / 256, 256>>>();
    layernorm_v2_kernel<<<grid, TPB, SMEM_BYTES>>>(x, alpha, beta, out);
}

// round 6
// speedup vs baseline: 1.3987x; 1.3987x over previous
#include <cuda_runtime.h>
#include <cuda_bf16.h>
#include <cstddef>

#define COL   4096
#define TPB   512
#define NW    (TPB/32)     // 16 warps
#define RPB   8            // rows per block, software-pipelined

__global__ __launch_bounds__(TPB, 2) void layernorm_v2_kernel(
    const float* __restrict__ x,
    const float* __restrict__ alpha,
    const float* __restrict__ beta,
    float* __restrict__ out)
{
    __shared__ float wsum[NW];
    __shared__ float wvar[NW];

    const int tid  = threadIdx.x;
    const int lane = tid & 31;
    const int wid  = tid >> 5;

    // thread owns elements [8t, 8t+7] -> float4 indices 2t, 2t+1
    const int f4a = 2 * tid;
    const int f4b = 2 * tid + 1;

    // reciprocals 1/(i+1) for this thread's fixed positions (once per block)
    const int e0 = 8 * tid;
    float r0x = 1.0f / (float)(e0 + 1);
    float r0y = 1.0f / (float)(e0 + 2);
    float r0z = 1.0f / (float)(e0 + 3);
    float r0w = 1.0f / (float)(e0 + 4);
    float r1x = 1.0f / (float)(e0 + 5);
    float r1y = 1.0f / (float)(e0 + 6);
    float r1z = 1.0f / (float)(e0 + 7);
    float r1w = 1.0f / (float)(e0 + 8);
    const float C = ((r0x * r0x + r0y * r0y) + (r0z * r0z + r0w * r0w))
                  + ((r1x * r1x + r1y * r1y) + (r1z * r1z + r1w * r1w));

    const float al = __ldg(alpha);
    const float be = __ldg(beta);

    const size_t row0 = (size_t)blockIdx.x * RPB;

    // prologue: load first row
    float4 a0 = ((const float4*)(x + row0 * COL))[f4a];
    float4 a1 = ((const float4*)(x + row0 * COL))[f4b];

    #pragma unroll 1
    for (int k = 0; k < RPB; ++k) {
        // prefetch next row before any barrier (LDG issue crosses BAR.SYNC)
        float4 b0, b1;
        if (k + 1 < RPB) {
            const float* xn = x + (row0 + k + 1) * COL;
            b0 = ((const float4*)xn)[f4a];
            b1 = ((const float4*)xn)[f4b];
        }

        // local inclusive scan of the 8-chunk
        const float p0 = a0.x;
        const float p1 = p0 + a0.y;
        const float p2 = p1 + a0.z;
        const float p3 = p2 + a0.w;
        const float p4 = p3 + a1.x;
        const float p5 = p4 + a1.y;
        const float p6 = p5 + a1.z;
        const float p7 = p6 + a1.w;
        const float tot = p7;

        // warp inclusive scan of thread totals...
        float v = tot;
        float s1v = __shfl_up_sync(0xffffffffu, v, 1);
        if (lane >= 1) v += s1v;
        // ...interleaved with barrier-independent A,B accumulators
        // a_i = x_i - p_i*r_i  (residual vs LOCAL running mean)
        const float q0 = a0.x - p0 * r0x;
        const float q1 = a0.y - p1 * r0y;
        float s2v = __shfl_up_sync(0xffffffffu, v, 2);
        if (lane >= 2) v += s2v;
        const float q2 = a0.z - p2 * r0z;
        const float q3 = a0.w - p3 * r0w;
        float s4v = __shfl_up_sync(0xffffffffu, v, 4);
        if (lane >= 4) v += s4v;
        const float q4 = a1.x - p4 * r1x;
        const float q5 = a1.y - p5 * r1y;
        float s8v = __shfl_up_sync(0xffffffffu, v, 8);
        if (lane >= 8) v += s8v;
        const float q6 = a1.z - p6 * r1z;
        const float q7 = a1.w - p7 * r1w;
        float s16v = __shfl_up_sync(0xffffffffu, v, 16);
        if (lane >= 16) v += s16v;

        const float A = ((q0 * q0 + q1 * q1) + (q2 * q2 + q3 * q3))
                      + ((q4 * q4 + q5 * q5) + (q6 * q6 + q7 * q7));
        const float B = ((q0 * r0x + q1 * r0y) + (q2 * r0z + q3 * r0w))
                      + ((q4 * r1x + q5 * r1y) + (q6 * r1z + q7 * r1w));

        if (lane == 31) wsum[wid] = v;
        __syncthreads();                       // BAR 1

        // redundant cross-warp scan: EVERY warp scans the 16 warp totals
        float t16 = (lane < NW) ? wsum[lane] : 0.0f;
        #pragma unroll
        for (int o = 1; o < NW; o <<= 1) {
            float n = __shfl_up_sync(0xffffffffu, t16, o);
            if (lane >= o) t16 += n;
        }
        const float total = __shfl_sync(0xffffffffu, t16, NW - 1);
        float woff = __shfl_sync(0xffffffffu, t16, (wid == 0) ? 0 : (wid - 1));
        if (wid == 0) woff = 0.0f;

        const float excl = woff + (v - tot);   // block-exclusive prefix

        // variance partial via precomputed A,B,C: Σ(a_i - e·r_i)^2
        float acc = A - 2.0f * excl * B + excl * excl * C;

        #pragma unroll
        for (int o = 16; o > 0; o >>= 1) acc += __shfl_xor_sync(0xffffffffu, acc, o);
        if (lane == 0) wvar[wid] = acc;
        __syncthreads();                       // BAR 2

        float u0 = 0.0f, u1 = 0.0f, u2 = 0.0f, u3 = 0.0f;
        #pragma unroll
        for (int w = 0; w < NW; w += 4) {
            u0 += wvar[w + 0];
            u1 += wvar[w + 1];
            u2 += wvar[w + 2];
            u3 += wvar[w + 3];
        }
        const float var   = ((u0 + u1) + (u2 + u3)) * (1.0f / (float)(COL - 1));
        const float mean  = total * (1.0f / (float)COL);
        const float scale = al * rsqrtf(var + 1e-5f);
        const float shift = be - mean * scale;     // out = x*scale + shift

        float* orow = out + (row0 + k) * COL;
        float4 o4;
        o4.x = a0.x * scale + shift;
        o4.y = a0.y * scale + shift;
        o4.z = a0.z * scale + shift;
        o4.w = a0.w * scale + shift;
        ((float4*)orow)[f4a] = o4;
        o4.x = a1.x * scale + shift;
        o4.y = a1.y * scale + shift;
        o4.z = a1.z * scale + shift;
        o4.w = a1.w * scale + shift;
        ((float4*)orow)[f4b] = o4;

        a0 = b0;
        a1 = b1;
    }
}

extern "C" void kernel_launch(void* const* d_in, const int* in_sizes, int n_in,
                              void* d_out, int out_size)
{
    const float* x     = (const float*)d_in[0];
    const float* alpha = (const float*)d_in[1];
    const float* beta  = (const float*)d_in[2];
    float*       out   = (float*)d_out;

    const int rows = in_sizes[0] / COL;
    const int grid = rows / RPB;               // 4096 blocks x 8 rows

    layernorm_v2_kernel<<<grid, TPB>>>(x, alpha, beta, out);
}